// round 14
// baseline (speedup 1.0000x reference)
#include <cuda_runtime.h>
#include <cuda_bf16.h>
#include <cuda_fp16.h>
#include <mma.h>
#include <cstdint>

using namespace nvcuda;

#define N_MAX 100000
#define N_PAD 100096              // = 391 * 256, multiple of CTA row tile
#define E_MAX 1600000
#define D_IN  256
#define H_DIM 128

// ---------------- scratch ---------------------------------------------------
__device__ __half g_xh [(size_t)N_PAD * H_DIM];   // x @ W1 (fp16, 25.6 MB)
__device__ float g_dinv[N_MAX];
__device__ int   g_deg [N_MAX];
__device__ int   g_rowptr[N_MAX + 1];
__device__ int   g_cur [N_MAX];
__device__ int   g_part[256];
__device__ int   g_esrc[E_MAX];                   // int32 src
__device__ int   g_edst[E_MAX];                   // int32 dst
__device__ int2  g_edge[E_MAX];                   // CSR: {src, bitcast coef}
__device__ float g_s   [N_MAX];
__device__ int   g_is64;
__device__ __align__(16) __nv_bfloat16 g_wh[D_IN * H_DIM];  // W1 hi, [k][n]
__device__ __align__(16) __nv_bfloat16 g_wl[D_IN * H_DIM];  // W1 lo, [k][n]

// ---------------- edge dtype detection -------------------------------------
__global__ void k_detect(const int* __restrict__ ei_words) {
    if (threadIdx.x == 0) {
        int is64 = 1;
        for (int i = 1; i < 128; i += 2)
            if (ei_words[i] != 0) { is64 = 0; break; }
        g_is64 = is64;
    }
}
__device__ __forceinline__ int load_edge(const void* ei, int is64, size_t idx) {
    if (is64) return (int)((const long long*)ei)[idx];
    return ((const int*)ei)[idx];
}

// ---------------- edge convert to int32 + degree histogram (fused) ---------
__global__ void k_cvt(const void* __restrict__ ei, int E) {
    int e = blockIdx.x * blockDim.x + threadIdx.x;
    if (e >= E) return;
    int is64 = g_is64;
    int src = load_edge(ei, is64, (size_t)e);
    int dst = load_edge(ei, is64, (size_t)E + e);
    g_esrc[e] = src;
    g_edst[e] = dst;
    atomicAdd(&g_deg[dst], 1);
}

// ---------------- W1 bf16 hi/lo split (native k x n layout) ----------------
__global__ void k_prep_w(const float* __restrict__ W1) {
    int i = blockIdx.x * blockDim.x + threadIdx.x;
    if (i >= D_IN * H_DIM) return;
    float v = W1[i];
    __nv_bfloat16 h = __float2bfloat16(v);
    g_wh[i] = h;
    g_wl[i] = __float2bfloat16(v - __bfloat162float(h));
}

// ---------------- degree / norm --------------------------------------------
__global__ void k_zero_deg(int N) {
    int i = blockIdx.x * blockDim.x + threadIdx.x;
    if (i < N) g_deg[i] = 0;
}
__global__ void k_dinv(int N) {
    int i = blockIdx.x * blockDim.x + threadIdx.x;
    if (i < N) g_dinv[i] = rsqrtf((float)(g_deg[i] + 1));
}

// ---------------- multi-block scan -----------------------------------------
__global__ void k_scan1(int N) {
    __shared__ int sh[256];
    int b = blockIdx.x, t = threadIdx.x;
    int i0 = b * 1024 + t * 4;
    int v0 = (i0 + 0 < N) ? g_deg[i0 + 0] : 0;
    int v1 = (i0 + 1 < N) ? g_deg[i0 + 1] : 0;
    int v2 = (i0 + 2 < N) ? g_deg[i0 + 2] : 0;
    int v3 = (i0 + 3 < N) ? g_deg[i0 + 3] : 0;
    int s = v0 + v1 + v2 + v3;
    sh[t] = s;
    __syncthreads();
#pragma unroll
    for (int off = 1; off < 256; off <<= 1) {
        int add = (t >= off) ? sh[t - off] : 0;
        __syncthreads();
        sh[t] += add;
        __syncthreads();
    }
    int excl = sh[t] - s;
    if (i0 + 0 < N) { g_rowptr[i0 + 0] = excl; excl += v0; }
    if (i0 + 1 < N) { g_rowptr[i0 + 1] = excl; excl += v1; }
    if (i0 + 2 < N) { g_rowptr[i0 + 2] = excl; excl += v2; }
    if (i0 + 3 < N) { g_rowptr[i0 + 3] = excl; }
    if (t == 255) g_part[b] = sh[255];
}
__global__ void k_scan2(int nb, int N) {
    __shared__ int sh[128];
    int t = threadIdx.x;
    int v = (t < nb) ? g_part[t] : 0;
    sh[t] = v;
    __syncthreads();
#pragma unroll
    for (int off = 1; off < 128; off <<= 1) {
        int add = (t >= off) ? sh[t - off] : 0;
        __syncthreads();
        sh[t] += add;
        __syncthreads();
    }
    if (t < nb) g_part[t] = sh[t] - v;
    if (t == 127) g_rowptr[N] = sh[127];
}
__global__ void k_scan3(int N) {
    int i = blockIdx.x * blockDim.x + threadIdx.x;
    if (i < N) {
        int r = g_rowptr[i] + g_part[i >> 10];
        g_rowptr[i] = r;
        g_cur[i] = r;
    }
}

// ---------------- counting-sort scatter (int32 inputs, packed edge) --------
__global__ void k_scatter(int E) {
    int e = blockIdx.x * blockDim.x + threadIdx.x;
    if (e >= E) return;
    int src = g_esrc[e];
    int dst = g_edst[e];
    int pos = atomicAdd(&g_cur[dst], 1);
    g_edge[pos] = make_int2(src, __float_as_int(g_dinv[src]));
}

// ---------------- wmma bf16-split GEMM: g_xh = fp16(x @ W1) ----------------
// CTA tile 256x128, 256 threads = 8 warps in 4x2; warp tile 64x64.
// Splits: hi*hi + hi*lo + lo*hi (fp32 accum); lo*lo dropped (~2^-18).
#define LDA 72      // 64 + 8 pad (bf16 elems)
#define LDB 136     // 128 + 8 pad
#define LDC 132     // 128 + 4 pad (fp32 elems, epilogue staging)
#define SM_AHI 0
#define SM_ALO (SM_AHI + 256 * LDA * 2)            // 36864
#define SM_BHI (SM_ALO + 256 * LDA * 2)            // 73728
#define SM_BLO (SM_BHI + 64 * LDB * 2)             // 91136
#define SM_TOTAL (SM_BLO + 64 * LDB * 2)           // 108544

__device__ __forceinline__ uint32_t pk2(__nv_bfloat16 a, __nv_bfloat16 b) {
    __nv_bfloat162 t(a, b);
    return *(uint32_t*)&t;
}

__global__ __launch_bounds__(256) void k_gemm(const float* __restrict__ A, int M) {
    extern __shared__ char sm[];
    __nv_bfloat16* As_hi = (__nv_bfloat16*)(sm + SM_AHI);
    __nv_bfloat16* As_lo = (__nv_bfloat16*)(sm + SM_ALO);
    __nv_bfloat16* Bs_hi = (__nv_bfloat16*)(sm + SM_BHI);
    __nv_bfloat16* Bs_lo = (__nv_bfloat16*)(sm + SM_BLO);

    int tid = threadIdx.x;
    int wid = tid >> 5;
    int wm = wid >> 1;          // 0..3 -> 64-row slab
    int wn = wid & 1;           // 0..1 -> 64-col slab
    int row0 = blockIdx.x * 256;

    wmma::fragment<wmma::accumulator, 16, 16, 16, float> acc[4][4];
#pragma unroll
    for (int i = 0; i < 4; i++)
#pragma unroll
        for (int j = 0; j < 4; j++) wmma::fill_fragment(acc[i][j], 0.0f);

    for (int c = 0; c < 4; c++) {
        int kb = c * 64;
        // stage A chunk [256 x 64] fp32 -> bf16 hi/lo  (4096 float4, 16 iters)
#pragma unroll
        for (int it = 0; it < 16; it++) {
            int f = it * 256 + tid;
            int r = f >> 4, c4 = f & 15;
            float4 v = make_float4(0.f, 0.f, 0.f, 0.f);
            int gr = row0 + r;
            if (gr < M) v = *(const float4*)(A + (size_t)gr * D_IN + kb + c4 * 4);
            __nv_bfloat16 h0 = __float2bfloat16(v.x);
            __nv_bfloat16 h1 = __float2bfloat16(v.y);
            __nv_bfloat16 h2 = __float2bfloat16(v.z);
            __nv_bfloat16 h3 = __float2bfloat16(v.w);
            __nv_bfloat16 l0 = __float2bfloat16(v.x - __bfloat162float(h0));
            __nv_bfloat16 l1 = __float2bfloat16(v.y - __bfloat162float(h1));
            __nv_bfloat16 l2 = __float2bfloat16(v.z - __bfloat162float(h2));
            __nv_bfloat16 l3 = __float2bfloat16(v.w - __bfloat162float(h3));
            int off = r * LDA + c4 * 4;
            *(uint2*)(As_hi + off) = make_uint2(pk2(h0, h1), pk2(h2, h3));
            *(uint2*)(As_lo + off) = make_uint2(pk2(l0, l1), pk2(l2, l3));
        }
        // stage B chunk [64 x 128] (1024 8-elem groups, 4 iters)
#pragma unroll
        for (int it = 0; it < 4; it++) {
            int g = it * 256 + tid;
            int k = g >> 4, n8 = g & 15;
            int src = (kb + k) * H_DIM + n8 * 8;
            int off = k * LDB + n8 * 8;
            *(uint4*)(Bs_hi + off) = *(const uint4*)(g_wh + src);
            *(uint4*)(Bs_lo + off) = *(const uint4*)(g_wl + src);
        }
        __syncthreads();

#pragma unroll
        for (int kk = 0; kk < 4; kk++) {
            wmma::fragment<wmma::matrix_a, 16, 16, 16, __nv_bfloat16,
                           wmma::row_major> a_hi[4], a_lo[4];
#pragma unroll
            for (int i = 0; i < 4; i++) {
                int aoff = (wm * 64 + i * 16) * LDA + kk * 16;
                wmma::load_matrix_sync(a_hi[i], As_hi + aoff, LDA);
                wmma::load_matrix_sync(a_lo[i], As_lo + aoff, LDA);
            }
#pragma unroll
            for (int j = 0; j < 4; j++) {
                wmma::fragment<wmma::matrix_b, 16, 16, 16, __nv_bfloat16,
                               wmma::row_major> b_hi, b_lo;
                int boff = (kk * 16) * LDB + wn * 64 + j * 16;
                wmma::load_matrix_sync(b_hi, Bs_hi + boff, LDB);
                wmma::load_matrix_sync(b_lo, Bs_lo + boff, LDB);
#pragma unroll
                for (int i = 0; i < 4; i++) {
                    wmma::mma_sync(acc[i][j], a_hi[i], b_hi, acc[i][j]);
                    wmma::mma_sync(acc[i][j], a_hi[i], b_lo, acc[i][j]);
                    wmma::mma_sync(acc[i][j], a_lo[i], b_hi, acc[i][j]);
                }
            }
        }
        __syncthreads();
    }

    // epilogue: two passes of 128 rows through smem, coalesced fp16 writes
    float* smc = (float*)sm;
#pragma unroll
    for (int p = 0; p < 2; p++) {
        if ((wm >> 1) == p) {
#pragma unroll
            for (int i = 0; i < 4; i++)
#pragma unroll
                for (int j = 0; j < 4; j++)
                    wmma::store_matrix_sync(
                        smc + ((wm & 1) * 64 + i * 16) * LDC + wn * 64 + j * 16,
                        acc[i][j], LDC, wmma::mem_row_major);
        }
        __syncthreads();
#pragma unroll
        for (int it = 0; it < 16; it++) {
            int idx = it * 256 + tid;        // float4 index: 128 rows x 32
            int r = idx >> 5, q = idx & 31;
            float4 v = *(float4*)(smc + r * LDC + q * 4);
            __half2 h0 = __floats2half2_rn(v.x, v.y);
            __half2 h1 = __floats2half2_rn(v.z, v.w);
            *(uint2*)(g_xh + (size_t)(row0 + p * 128 + r) * H_DIM + q * 4) =
                make_uint2(*(uint32_t*)&h0, *(uint32_t*)&h1);
        }
        __syncthreads();
    }
}

// ---------------- fused layer-1 aggregate + relu + W2 dot (fp16 gather) ----
// warp per dst node; 2-edge unroll with dual accumulators for gather MLP.
__global__ __launch_bounds__(256) void k_fused1(const float* __restrict__ b1,
                                                const float* __restrict__ W2,
                                                int N) {
    int gid  = blockIdx.x * blockDim.x + threadIdx.x;
    int v    = gid >> 5;
    int lane = gid & 31;
    if (v >= N) return;
    int beg = g_rowptr[v], end = g_rowptr[v + 1];
    int q = lane * 4;
    float4 acc0 = make_float4(0.f, 0.f, 0.f, 0.f);
    float4 acc1 = make_float4(0.f, 0.f, 0.f, 0.f);
    int j = beg;
    for (; j + 2 <= end; j += 2) {
        int2 e0 = g_edge[j];
        int2 e1 = g_edge[j + 1];
        uint2 u0 = *(const uint2*)(g_xh + (size_t)e0.x * H_DIM + q);
        uint2 u1 = *(const uint2*)(g_xh + (size_t)e1.x * H_DIM + q);
        float c0 = __int_as_float(e0.y), c1 = __int_as_float(e1.y);
        float2 a0 = __half22float2(*(__half2*)&u0.x);
        float2 a1 = __half22float2(*(__half2*)&u0.y);
        float2 b0f = __half22float2(*(__half2*)&u1.x);
        float2 b1f = __half22float2(*(__half2*)&u1.y);
        acc0.x = fmaf(c0, a0.x, acc0.x);
        acc0.y = fmaf(c0, a0.y, acc0.y);
        acc0.z = fmaf(c0, a1.x, acc0.z);
        acc0.w = fmaf(c0, a1.y, acc0.w);
        acc1.x = fmaf(c1, b0f.x, acc1.x);
        acc1.y = fmaf(c1, b0f.y, acc1.y);
        acc1.z = fmaf(c1, b1f.x, acc1.z);
        acc1.w = fmaf(c1, b1f.y, acc1.w);
    }
    if (j < end) {
        int2 e0 = g_edge[j];
        uint2 u0 = *(const uint2*)(g_xh + (size_t)e0.x * H_DIM + q);
        float c0 = __int_as_float(e0.y);
        float2 a0 = __half22float2(*(__half2*)&u0.x);
        float2 a1 = __half22float2(*(__half2*)&u0.y);
        acc0.x = fmaf(c0, a0.x, acc0.x);
        acc0.y = fmaf(c0, a0.y, acc0.y);
        acc0.z = fmaf(c0, a1.x, acc0.z);
        acc0.w = fmaf(c0, a1.y, acc0.w);
    }
    float4 acc = make_float4(acc0.x + acc1.x, acc0.y + acc1.y,
                             acc0.z + acc1.z, acc0.w + acc1.w);
    float d  = g_dinv[v];
    float d2 = d * d;
    uint2 su = *(const uint2*)(g_xh + (size_t)v * H_DIM + q);
    float2 s0 = __half22float2(*(__half2*)&su.x);
    float2 s1 = __half22float2(*(__half2*)&su.y);
    float4 bb = *(const float4*)&b1[q];
    float4 w  = *(const float4*)&W2[q];
    float sum = fmaxf(d * acc.x + d2 * s0.x + bb.x, 0.f) * w.x
              + fmaxf(d * acc.y + d2 * s0.y + bb.y, 0.f) * w.y
              + fmaxf(d * acc.z + d2 * s1.x + bb.z, 0.f) * w.z
              + fmaxf(d * acc.w + d2 * s1.y + bb.w, 0.f) * w.w;
#pragma unroll
    for (int off = 16; off; off >>= 1)
        sum += __shfl_xor_sync(0xffffffffu, sum, off);
    if (lane == 0) g_s[v] = sum;
}

// ---------------- layer-2: 8 lanes per dst node ----------------------------
__global__ __launch_bounds__(256) void k_out(const float* __restrict__ b2,
                                             float* __restrict__ out, int N) {
    int gid  = blockIdx.x * blockDim.x + threadIdx.x;
    int v    = gid >> 3;
    int ln   = gid & 7;
    if (v >= N) return;
    int beg = g_rowptr[v], end = g_rowptr[v + 1];
    float acc = 0.f;
    for (int j = beg + ln; j < end; j += 8) {
        int2 ec = g_edge[j];
        acc += __int_as_float(ec.y) * g_s[ec.x];
    }
#pragma unroll
    for (int off = 4; off; off >>= 1)
        acc += __shfl_xor_sync(0xffffffffu, acc, off);
    if (ln == 0) {
        float d = g_dinv[v];
        out[v] = d * acc + d * d * g_s[v] + b2[0];
    }
}

// ---------------- launch ----------------------------------------------------
extern "C" void kernel_launch(void* const* d_in, const int* in_sizes, int n_in,
                              void* d_out, int out_size) {
    const float* x  = (const float*)d_in[0];
    const void*  ei = d_in[1];
    const float* W1 = (const float*)d_in[2];
    const float* b1 = (const float*)d_in[3];
    const float* W2 = (const float*)d_in[4];
    const float* b2 = (const float*)d_in[5];
    float* out = (float*)d_out;

    int N = in_sizes[0] / D_IN;
    int E = in_sizes[1] / 2;
    int nb = (N + 1023) / 1024;

    static cudaStream_t s2;
    static cudaEvent_t evFork, evJoin;
    static int inited = 0;
    if (!inited) {
        cudaFuncSetAttribute(k_gemm, cudaFuncAttributeMaxDynamicSharedMemorySize,
                             SM_TOTAL);
        cudaStreamCreateWithFlags(&s2, cudaStreamNonBlocking);
        cudaEventCreateWithFlags(&evFork, cudaEventDisableTiming);
        cudaEventCreateWithFlags(&evJoin, cudaEventDisableTiming);
        inited = 1;
    }

    // launch #1..#4 submission order chosen so ncu (4th launch) profiles k_gemm
    k_prep_w<<<(D_IN * H_DIM + 255) / 256, 256>>>(W1);          // 1 (main)
    cudaEventRecord(evFork, 0);
    cudaStreamWaitEvent(s2, evFork, 0);
    k_detect<<<1, 32, 0, s2>>>((const int*)ei);                 // 2 (side)
    k_zero_deg<<<(N + 255) / 256, 256, 0, s2>>>(N);             // 3 (side)
    k_gemm<<<(N + 255) / 256, 256, SM_TOTAL>>>(x, N);           // 4 (main)

    // rest of side stream: edge cvt+hist, norms, scan, scatter
    k_cvt<<<(E + 255) / 256, 256, 0, s2>>>(ei, E);
    k_dinv<<<(N + 255) / 256, 256, 0, s2>>>(N);
    k_scan1<<<nb, 256, 0, s2>>>(N);
    k_scan2<<<1, 128, 0, s2>>>(nb, N);
    k_scan3<<<(N + 255) / 256, 256, 0, s2>>>(N);
    k_scatter<<<(E + 255) / 256, 256, 0, s2>>>(E);
    cudaEventRecord(evJoin, s2);

    cudaStreamWaitEvent(0, evJoin, 0);
    k_fused1<<<(N * 32 + 255) / 256, 256>>>(b1, W2, N);
    k_out<<<(N * 8 + 255) / 256, 256>>>(b2, out, N);
}

// round 17
// speedup vs baseline: 1.0799x; 1.0799x over previous
#include <cuda_runtime.h>
#include <cuda_bf16.h>
#include <cuda_fp16.h>
#include <mma.h>
#include <cstdint>

using namespace nvcuda;

#define N_MAX 100000
#define N_PAD 100096              // = 782 * 128, multiple of CTA row tile
#define E_MAX 1600000
#define D_IN  256
#define H_DIM 128

// ---------------- scratch ---------------------------------------------------
__device__ __half g_xh [(size_t)N_PAD * H_DIM];   // x @ W1 (fp16, 25.6 MB)
__device__ float g_dinv[N_MAX];
__device__ int   g_deg [N_MAX];
__device__ int   g_rowptr[N_MAX + 1];
__device__ int   g_cur [N_MAX];
__device__ int   g_part[256];
__device__ int   g_esrc[E_MAX];                   // int32 src
__device__ int   g_edst[E_MAX];                   // int32 dst
__device__ int2  g_edge[E_MAX];                   // CSR: {src, bitcast coef}
__device__ float g_s   [N_MAX];
__device__ int   g_is64;
__device__ __align__(16) __nv_bfloat16 g_wh[D_IN * H_DIM];  // W1 hi, [k][n]
__device__ __align__(16) __nv_bfloat16 g_wl[D_IN * H_DIM];  // W1 lo, [k][n]

// ---------------- edge dtype detection -------------------------------------
__global__ void k_detect(const int* __restrict__ ei_words) {
    if (threadIdx.x == 0) {
        int is64 = 1;
        for (int i = 1; i < 128; i += 2)
            if (ei_words[i] != 0) { is64 = 0; break; }
        g_is64 = is64;
    }
}
__device__ __forceinline__ int load_edge(const void* ei, int is64, size_t idx) {
    if (is64) return (int)((const long long*)ei)[idx];
    return ((const int*)ei)[idx];
}

// ---------------- edge convert to int32 + degree histogram (fused) ---------
__global__ void k_cvt(const void* __restrict__ ei, int E) {
    int e = blockIdx.x * blockDim.x + threadIdx.x;
    if (e >= E) return;
    int is64 = g_is64;
    int src = load_edge(ei, is64, (size_t)e);
    int dst = load_edge(ei, is64, (size_t)E + e);
    g_esrc[e] = src;
    g_edst[e] = dst;
    atomicAdd(&g_deg[dst], 1);
}

// ---------------- W1 bf16 hi/lo split (native k x n layout) ----------------
__global__ void k_prep_w(const float* __restrict__ W1) {
    int i = blockIdx.x * blockDim.x + threadIdx.x;
    if (i >= D_IN * H_DIM) return;
    float v = W1[i];
    __nv_bfloat16 h = __float2bfloat16(v);
    g_wh[i] = h;
    g_wl[i] = __float2bfloat16(v - __bfloat162float(h));
}

// ---------------- degree / norm --------------------------------------------
__global__ void k_zero_deg(int N) {
    int i = blockIdx.x * blockDim.x + threadIdx.x;
    if (i < N) g_deg[i] = 0;
}
__global__ void k_dinv(int N) {
    int i = blockIdx.x * blockDim.x + threadIdx.x;
    if (i < N) g_dinv[i] = rsqrtf((float)(g_deg[i] + 1));
}

// ---------------- multi-block scan -----------------------------------------
__global__ void k_scan1(int N) {
    __shared__ int sh[256];
    int b = blockIdx.x, t = threadIdx.x;
    int i0 = b * 1024 + t * 4;
    int v0 = (i0 + 0 < N) ? g_deg[i0 + 0] : 0;
    int v1 = (i0 + 1 < N) ? g_deg[i0 + 1] : 0;
    int v2 = (i0 + 2 < N) ? g_deg[i0 + 2] : 0;
    int v3 = (i0 + 3 < N) ? g_deg[i0 + 3] : 0;
    int s = v0 + v1 + v2 + v3;
    sh[t] = s;
    __syncthreads();
#pragma unroll
    for (int off = 1; off < 256; off <<= 1) {
        int add = (t >= off) ? sh[t - off] : 0;
        __syncthreads();
        sh[t] += add;
        __syncthreads();
    }
    int excl = sh[t] - s;
    if (i0 + 0 < N) { g_rowptr[i0 + 0] = excl; excl += v0; }
    if (i0 + 1 < N) { g_rowptr[i0 + 1] = excl; excl += v1; }
    if (i0 + 2 < N) { g_rowptr[i0 + 2] = excl; excl += v2; }
    if (i0 + 3 < N) { g_rowptr[i0 + 3] = excl; }
    if (t == 255) g_part[b] = sh[255];
}
__global__ void k_scan2(int nb, int N) {
    __shared__ int sh[128];
    int t = threadIdx.x;
    int v = (t < nb) ? g_part[t] : 0;
    sh[t] = v;
    __syncthreads();
#pragma unroll
    for (int off = 1; off < 128; off <<= 1) {
        int add = (t >= off) ? sh[t - off] : 0;
        __syncthreads();
        sh[t] += add;
        __syncthreads();
    }
    if (t < nb) g_part[t] = sh[t] - v;
    if (t == 127) g_rowptr[N] = sh[127];
}
__global__ void k_scan3(int N) {
    int i = blockIdx.x * blockDim.x + threadIdx.x;
    if (i < N) {
        int r = g_rowptr[i] + g_part[i >> 10];
        g_rowptr[i] = r;
        g_cur[i] = r;
    }
}

// ---------------- counting-sort scatter (int32 inputs, packed edge) --------
__global__ void k_scatter(int E) {
    int e = blockIdx.x * blockDim.x + threadIdx.x;
    if (e >= E) return;
    int src = g_esrc[e];
    int dst = g_edst[e];
    int pos = atomicAdd(&g_cur[dst], 1);
    g_edge[pos] = make_int2(src, __float_as_int(g_dinv[src]));
}

// ---------------- wmma bf16-split GEMM: g_xh = fp16(x @ W1) ----------------
// CTA tile 128x128, 256 threads = 8 warps in 4x2; warp tile 32x64.
// acc[2][4] = 64 regs -> fits 128-reg budget -> 2 CTAs/SM (occupancy pipelining).
// Splits: hi*hi + hi*lo + lo*hi (fp32 accum); lo*lo dropped (~2^-18).
#define LDA 72      // 64 + 8 pad (bf16 elems)
#define LDB 136     // 128 + 8 pad
#define LDC 132     // 128 + 4 pad (fp32 elems, epilogue staging)
#define SM_AHI 0
#define SM_ALO (SM_AHI + 128 * LDA * 2)            // 18432
#define SM_BHI (SM_ALO + 128 * LDA * 2)            // 36864
#define SM_BLO (SM_BHI + 64 * LDB * 2)             // 54272
#define SM_TOTAL (SM_BLO + 64 * LDB * 2)           // 71680 -> 2 CTAs/SM

__device__ __forceinline__ uint32_t pk2(__nv_bfloat16 a, __nv_bfloat16 b) {
    __nv_bfloat162 t(a, b);
    return *(uint32_t*)&t;
}

__global__ __launch_bounds__(256, 2) void k_gemm(const float* __restrict__ A, int M) {
    extern __shared__ char sm[];
    __nv_bfloat16* As_hi = (__nv_bfloat16*)(sm + SM_AHI);
    __nv_bfloat16* As_lo = (__nv_bfloat16*)(sm + SM_ALO);
    __nv_bfloat16* Bs_hi = (__nv_bfloat16*)(sm + SM_BHI);
    __nv_bfloat16* Bs_lo = (__nv_bfloat16*)(sm + SM_BLO);

    int tid = threadIdx.x;
    int wid = tid >> 5;
    int wm = wid >> 1;          // 0..3 -> 32-row slab
    int wn = wid & 1;           // 0..1 -> 64-col slab
    int row0 = blockIdx.x * 128;

    wmma::fragment<wmma::accumulator, 16, 16, 16, float> acc[2][4];
#pragma unroll
    for (int i = 0; i < 2; i++)
#pragma unroll
        for (int j = 0; j < 4; j++) wmma::fill_fragment(acc[i][j], 0.0f);

    for (int c = 0; c < 4; c++) {
        int kb = c * 64;
        // stage A chunk [128 x 64] fp32 -> bf16 hi/lo  (2048 float4, 8 iters)
#pragma unroll
        for (int it = 0; it < 8; it++) {
            int f = it * 256 + tid;
            int r = f >> 4, c4 = f & 15;
            float4 v = make_float4(0.f, 0.f, 0.f, 0.f);
            int gr = row0 + r;
            if (gr < M) v = *(const float4*)(A + (size_t)gr * D_IN + kb + c4 * 4);
            __nv_bfloat16 h0 = __float2bfloat16(v.x);
            __nv_bfloat16 h1 = __float2bfloat16(v.y);
            __nv_bfloat16 h2 = __float2bfloat16(v.z);
            __nv_bfloat16 h3 = __float2bfloat16(v.w);
            __nv_bfloat16 l0 = __float2bfloat16(v.x - __bfloat162float(h0));
            __nv_bfloat16 l1 = __float2bfloat16(v.y - __bfloat162float(h1));
            __nv_bfloat16 l2 = __float2bfloat16(v.z - __bfloat162float(h2));
            __nv_bfloat16 l3 = __float2bfloat16(v.w - __bfloat162float(h3));
            int off = r * LDA + c4 * 4;
            *(uint2*)(As_hi + off) = make_uint2(pk2(h0, h1), pk2(h2, h3));
            *(uint2*)(As_lo + off) = make_uint2(pk2(l0, l1), pk2(l2, l3));
        }
        // stage B chunk [64 x 128] (1024 8-elem groups, 4 iters)
#pragma unroll
        for (int it = 0; it < 4; it++) {
            int g = it * 256 + tid;
            int k = g >> 4, n8 = g & 15;
            int src = (kb + k) * H_DIM + n8 * 8;
            int off = k * LDB + n8 * 8;
            *(uint4*)(Bs_hi + off) = *(const uint4*)(g_wh + src);
            *(uint4*)(Bs_lo + off) = *(const uint4*)(g_wl + src);
        }
        __syncthreads();

#pragma unroll
        for (int kk = 0; kk < 4; kk++) {
            wmma::fragment<wmma::matrix_a, 16, 16, 16, __nv_bfloat16,
                           wmma::row_major> a_hi[2], a_lo[2];
#pragma unroll
            for (int i = 0; i < 2; i++) {
                int aoff = (wm * 32 + i * 16) * LDA + kk * 16;
                wmma::load_matrix_sync(a_hi[i], As_hi + aoff, LDA);
                wmma::load_matrix_sync(a_lo[i], As_lo + aoff, LDA);
            }
#pragma unroll
            for (int j = 0; j < 4; j++) {
                wmma::fragment<wmma::matrix_b, 16, 16, 16, __nv_bfloat16,
                               wmma::row_major> b_hi, b_lo;
                int boff = (kk * 16) * LDB + wn * 64 + j * 16;
                wmma::load_matrix_sync(b_hi, Bs_hi + boff, LDB);
                wmma::load_matrix_sync(b_lo, Bs_lo + boff, LDB);
#pragma unroll
                for (int i = 0; i < 2; i++) {
                    wmma::mma_sync(acc[i][j], a_hi[i], b_hi, acc[i][j]);
                    wmma::mma_sync(acc[i][j], a_hi[i], b_lo, acc[i][j]);
                    wmma::mma_sync(acc[i][j], a_lo[i], b_hi, acc[i][j]);
                }
            }
        }
        __syncthreads();
    }

    // epilogue: stage fp32 accs in smem (67.6KB <= 70KB), coalesced fp16 write
    float* smc = (float*)sm;
#pragma unroll
    for (int i = 0; i < 2; i++)
#pragma unroll
        for (int j = 0; j < 4; j++)
            wmma::store_matrix_sync(
                smc + (wm * 32 + i * 16) * LDC + wn * 64 + j * 16,
                acc[i][j], LDC, wmma::mem_row_major);
    __syncthreads();
#pragma unroll
    for (int it = 0; it < 16; it++) {
        int idx = it * 256 + tid;            // float4 index: 128 rows x 32
        int r = idx >> 5, q = idx & 31;
        float4 v = *(float4*)(smc + r * LDC + q * 4);
        __half2 h0 = __floats2half2_rn(v.x, v.y);
        __half2 h1 = __floats2half2_rn(v.z, v.w);
        *(uint2*)(g_xh + (size_t)(row0 + r) * H_DIM + q * 4) =
            make_uint2(*(uint32_t*)&h0, *(uint32_t*)&h1);
    }
}

// ---------------- fused layer-1 aggregate + relu + W2 dot (fp16 gather) ----
// warp per dst node; 2-edge unroll with dual accumulators for gather MLP.
__global__ __launch_bounds__(256) void k_fused1(const float* __restrict__ b1,
                                                const float* __restrict__ W2,
                                                int N) {
    int gid  = blockIdx.x * blockDim.x + threadIdx.x;
    int v    = gid >> 5;
    int lane = gid & 31;
    if (v >= N) return;
    int beg = g_rowptr[v], end = g_rowptr[v + 1];
    int q = lane * 4;
    float4 acc0 = make_float4(0.f, 0.f, 0.f, 0.f);
    float4 acc1 = make_float4(0.f, 0.f, 0.f, 0.f);
    int j = beg;
    for (; j + 2 <= end; j += 2) {
        int2 e0 = g_edge[j];
        int2 e1 = g_edge[j + 1];
        uint2 u0 = *(const uint2*)(g_xh + (size_t)e0.x * H_DIM + q);
        uint2 u1 = *(const uint2*)(g_xh + (size_t)e1.x * H_DIM + q);
        float c0 = __int_as_float(e0.y), c1 = __int_as_float(e1.y);
        float2 a0 = __half22float2(*(__half2*)&u0.x);
        float2 a1 = __half22float2(*(__half2*)&u0.y);
        float2 b0f = __half22float2(*(__half2*)&u1.x);
        float2 b1f = __half22float2(*(__half2*)&u1.y);
        acc0.x = fmaf(c0, a0.x, acc0.x);
        acc0.y = fmaf(c0, a0.y, acc0.y);
        acc0.z = fmaf(c0, a1.x, acc0.z);
        acc0.w = fmaf(c0, a1.y, acc0.w);
        acc1.x = fmaf(c1, b0f.x, acc1.x);
        acc1.y = fmaf(c1, b0f.y, acc1.y);
        acc1.z = fmaf(c1, b1f.x, acc1.z);
        acc1.w = fmaf(c1, b1f.y, acc1.w);
    }
    if (j < end) {
        int2 e0 = g_edge[j];
        uint2 u0 = *(const uint2*)(g_xh + (size_t)e0.x * H_DIM + q);
        float c0 = __int_as_float(e0.y);
        float2 a0 = __half22float2(*(__half2*)&u0.x);
        float2 a1 = __half22float2(*(__half2*)&u0.y);
        acc0.x = fmaf(c0, a0.x, acc0.x);
        acc0.y = fmaf(c0, a0.y, acc0.y);
        acc0.z = fmaf(c0, a1.x, acc0.z);
        acc0.w = fmaf(c0, a1.y, acc0.w);
    }
    float4 acc = make_float4(acc0.x + acc1.x, acc0.y + acc1.y,
                             acc0.z + acc1.z, acc0.w + acc1.w);
    float d  = g_dinv[v];
    float d2 = d * d;
    uint2 su = *(const uint2*)(g_xh + (size_t)v * H_DIM + q);
    float2 s0 = __half22float2(*(__half2*)&su.x);
    float2 s1 = __half22float2(*(__half2*)&su.y);
    float4 bb = *(const float4*)&b1[q];
    float4 w  = *(const float4*)&W2[q];
    float sum = fmaxf(d * acc.x + d2 * s0.x + bb.x, 0.f) * w.x
              + fmaxf(d * acc.y + d2 * s0.y + bb.y, 0.f) * w.y
              + fmaxf(d * acc.z + d2 * s1.x + bb.z, 0.f) * w.z
              + fmaxf(d * acc.w + d2 * s1.y + bb.w, 0.f) * w.w;
#pragma unroll
    for (int off = 16; off; off >>= 1)
        sum += __shfl_xor_sync(0xffffffffu, sum, off);
    if (lane == 0) g_s[v] = sum;
}

// ---------------- layer-2: 8 lanes per dst node ----------------------------
__global__ __launch_bounds__(256) void k_out(const float* __restrict__ b2,
                                             float* __restrict__ out, int N) {
    int gid  = blockIdx.x * blockDim.x + threadIdx.x;
    int v    = gid >> 3;
    int ln   = gid & 7;
    if (v >= N) return;
    int beg = g_rowptr[v], end = g_rowptr[v + 1];
    float acc = 0.f;
    for (int j = beg + ln; j < end; j += 8) {
        int2 ec = g_edge[j];
        acc += __int_as_float(ec.y) * g_s[ec.x];
    }
#pragma unroll
    for (int off = 4; off; off >>= 1)
        acc += __shfl_xor_sync(0xffffffffu, acc, off);
    if (ln == 0) {
        float d = g_dinv[v];
        out[v] = d * acc + d * d * g_s[v] + b2[0];
    }
}

// ---------------- launch ----------------------------------------------------
extern "C" void kernel_launch(void* const* d_in, const int* in_sizes, int n_in,
                              void* d_out, int out_size) {
    const float* x  = (const float*)d_in[0];
    const void*  ei = d_in[1];
    const float* W1 = (const float*)d_in[2];
    const float* b1 = (const float*)d_in[3];
    const float* W2 = (const float*)d_in[4];
    const float* b2 = (const float*)d_in[5];
    float* out = (float*)d_out;

    int N = in_sizes[0] / D_IN;
    int E = in_sizes[1] / 2;
    int nb = (N + 1023) / 1024;

    static cudaStream_t s2;
    static cudaEvent_t evFork, evJoin;
    static int inited = 0;
    if (!inited) {
        cudaFuncSetAttribute(k_gemm, cudaFuncAttributeMaxDynamicSharedMemorySize,
                             SM_TOTAL);
        cudaStreamCreateWithFlags(&s2, cudaStreamNonBlocking);
        cudaEventCreateWithFlags(&evFork, cudaEventDisableTiming);
        cudaEventCreateWithFlags(&evJoin, cudaEventDisableTiming);
        inited = 1;
    }

    // launch #1..#4 submission order chosen so ncu (4th launch) profiles k_gemm
    k_prep_w<<<(D_IN * H_DIM + 255) / 256, 256>>>(W1);          // 1 (main)
    cudaEventRecord(evFork, 0);
    cudaStreamWaitEvent(s2, evFork, 0);
    k_detect<<<1, 32, 0, s2>>>((const int*)ei);                 // 2 (side)
    k_zero_deg<<<(N + 255) / 256, 256, 0, s2>>>(N);             // 3 (side)
    k_gemm<<<(N + 127) / 128, 256, SM_TOTAL>>>(x, N);           // 4 (main)

    // rest of side stream: edge cvt+hist, norms, scan, scatter
    k_cvt<<<(E + 255) / 256, 256, 0, s2>>>(ei, E);
    k_dinv<<<(N + 255) / 256, 256, 0, s2>>>(N);
    k_scan1<<<nb, 256, 0, s2>>>(N);
    k_scan2<<<1, 128, 0, s2>>>(nb, N);
    k_scan3<<<(N + 255) / 256, 256, 0, s2>>>(N);
    k_scatter<<<(E + 255) / 256, 256, 0, s2>>>(E);
    cudaEventRecord(evJoin, s2);

    cudaStreamWaitEvent(0, evJoin, 0);
    k_fused1<<<(N * 32 + 255) / 256, 256>>>(b1, W2, N);
    k_out<<<(N * 8 + 255) / 256, 256>>>(b2, out, N);
}